// round 1
// baseline (speedup 1.0000x reference)
#include <cuda_runtime.h>
#include <cuda_bf16.h>

// InnerProduct_541165879452
// lp[r,p] = sum_f w[p,f]^2 * sum_e x[r,f,e]^2
// x: [R=32768, F=64, E=16] f32 (row = 1024 contiguous floats = 4 KB)
// w: [P=10, F=64] f32
// out: [R, P] f32
//
// One warp per row, fully-coalesced float4 loads (4 wavefronts per LDG.128),
// quad shuffle-reduce to assemble xsq[f], per-lane static ownership of 2 f's,
// register-resident squared weights, butterfly reduce of 10 accumulators.

#define F_DIM 64
#define E_DIM 16
#define P_DIM 10
#define ROW_FLOATS (F_DIM * E_DIM)   // 1024
#define WARPS_PER_BLOCK 8

__global__ __launch_bounds__(32 * WARPS_PER_BLOCK)
void ip_kernel(const float* __restrict__ x,
               const float* __restrict__ w,
               float* __restrict__ out,
               int R)
{
    const int wid  = threadIdx.x >> 5;
    const int lane = threadIdx.x & 31;
    const int row  = blockIdx.x * WARPS_PER_BLOCK + wid;
    if (row >= R) return;

    const int c = lane >> 2;   // 0..7  : which f-slot within an i-group
    const int q = lane & 3;    // 0..3  : which i-pair this lane will own

    // This lane will own f_a = 16q + c and f_b = 16q + 8 + c
    // (i.e. i = 2q and i = 2q+1 in f = 8i + c). Covers all 64 f exactly once.
    const int f_a = 16 * q + c;
    const int f_b = f_a + 8;

    // Pre-squared weights for this lane's two features (L2-resident, 20 LDG once).
    float wa[P_DIM], wb[P_DIM];
#pragma unroll
    for (int p = 0; p < P_DIM; p++) {
        float va = w[p * F_DIM + f_a];
        float vb = w[p * F_DIM + f_b];
        wa[p] = va * va;
        wb[p] = vb * vb;
    }

    // Coalesced row load: lane l reads float4 #(i*32 + l).
    // Quarter j covers elements [4j, 4j+4) of the row; f = j >> 2 = 8i + (l>>2).
    const float4* __restrict__ xr =
        reinterpret_cast<const float4*>(x + (size_t)row * ROW_FLOATS);

    float s[8];
#pragma unroll
    for (int i = 0; i < 8; i++) {
        float4 v = xr[i * 32 + lane];
        s[i] = v.x * v.x + v.y * v.y + v.z * v.z + v.w * v.w;
    }

    // Quad reduce: lanes {4c..4c+3} share f for every i -> after xor 1,2
    // every lane holds the full xsq[8i + c] for its c.
#pragma unroll
    for (int i = 0; i < 8; i++) {
        s[i] += __shfl_xor_sync(0xffffffffu, s[i], 1);
        s[i] += __shfl_xor_sync(0xffffffffu, s[i], 2);
    }

    // Static (no dynamic register index!) selection of this lane's two xsq values.
    float xa = (q == 0) ? s[0] : (q == 1) ? s[2] : (q == 2) ? s[4] : s[6];
    float xb = (q == 0) ? s[1] : (q == 1) ? s[3] : (q == 2) ? s[5] : s[7];

    // Per-lane projection onto the 10 prototypes.
    float acc[P_DIM];
#pragma unroll
    for (int p = 0; p < P_DIM; p++)
        acc[p] = fmaf(xa, wa[p], xb * wb[p]);

    // Butterfly reduce across the warp (each lane held distinct f's).
#pragma unroll
    for (int off = 16; off >= 1; off >>= 1) {
#pragma unroll
        for (int p = 0; p < P_DIM; p++)
            acc[p] += __shfl_xor_sync(0xffffffffu, acc[p], off);
    }

    // Row offset = 40*row bytes -> 8B aligned: 5x STG.64 from lane 0.
    if (lane == 0) {
        float2* o = reinterpret_cast<float2*>(out + (size_t)row * P_DIM);
#pragma unroll
        for (int p = 0; p < 5; p++)
            o[p] = make_float2(acc[2 * p], acc[2 * p + 1]);
    }
}

extern "C" void kernel_launch(void* const* d_in, const int* in_sizes, int n_in,
                              void* d_out, int out_size)
{
    const float* x = (const float*)d_in[0];
    const float* w = (const float*)d_in[1];
    float* out = (float*)d_out;

    const int R = in_sizes[0] / ROW_FLOATS;            // 32768
    const int blocks = (R + WARPS_PER_BLOCK - 1) / WARPS_PER_BLOCK;  // 4096

    ip_kernel<<<blocks, 32 * WARPS_PER_BLOCK>>>(x, w, out, R);
}